// round 1
// baseline (speedup 1.0000x reference)
#include <cuda_runtime.h>
#include <cstdint>

// Problem constants (match reference setup_inputs)
#define NNODES 50000
#define NEDGES 640000
// IN_DIM = 128, HID = 128, OUT = 64

// ---------------------------------------------------------------------------
// Device scratch (allocation-free rule: __device__ globals)
// ---------------------------------------------------------------------------
// Layer-1 combined GEMM output: [N, 256] = [x@Ws1^T | x@Wn1^T]
__device__ float4 g_C1[NNODES * 64];      // 51.2 MB
// Layer-1 neighbor aggregation accumulator: [N, 128]
__device__ float4 g_AGG1[NNODES * 32];    // 25.6 MB
// Hidden activations after layer 1: [N, 128]
__device__ float4 g_H1[NNODES * 32];      // 25.6 MB
// Layer-2 combined GEMM output: [N, 128] = [h1@Ws2^T | h1@Wn2^T]
__device__ float4 g_C2[NNODES * 32];      // 25.6 MB
// Layer-2 aggregation accumulator: [N, 64]
__device__ float4 g_AGG2[NNODES * 16];    // 12.8 MB
// Degrees
__device__ float  g_DEG[NNODES];
// Transposed+concatenated weights: WT1[k][t], k<128, t<256 (t<128: Ws1, else Wn1)
__device__ float  g_WT1[128 * 256];
// WT2[k][t], k<128, t<128 (t<64: Ws2, else Wn2)
__device__ float  g_WT2[128 * 128];

// ---------------------------------------------------------------------------
// Packed fp32x2 FMA (Blackwell, PTX ISA 8.6+, sm_100+)
// ---------------------------------------------------------------------------
__device__ __forceinline__ float2 ffma2(float2 a, float2 b, float2 c) {
    float2 d;
    asm("{\n\t"
        ".reg .b64 ra, rb, rc, rd;\n\t"
        "mov.b64 ra, {%2, %3};\n\t"
        "mov.b64 rb, {%4, %5};\n\t"
        "mov.b64 rc, {%6, %7};\n\t"
        "fma.rn.f32x2 rd, ra, rb, rc;\n\t"
        "mov.b64 {%0, %1}, rd;\n\t"
        "}"
        : "=f"(d.x), "=f"(d.y)
        : "f"(a.x), "f"(a.y), "f"(b.x), "f"(b.y), "f"(c.x), "f"(c.y));
    return d;
}

// ---------------------------------------------------------------------------
// Zero-fill
// ---------------------------------------------------------------------------
__global__ void zero4_kernel(float4* __restrict__ p, int n4) {
    int i = blockIdx.x * blockDim.x + threadIdx.x;
    int stride = gridDim.x * blockDim.x;
    float4 z = make_float4(0.f, 0.f, 0.f, 0.f);
    for (; i < n4; i += stride) p[i] = z;
}

// ---------------------------------------------------------------------------
// Build transposed weight matrices in scratch
// ---------------------------------------------------------------------------
__global__ void prep_weights_kernel(const float* __restrict__ Ws1,
                                    const float* __restrict__ Wn1,
                                    const float* __restrict__ Ws2,
                                    const float* __restrict__ Wn2) {
    int i = blockIdx.x * blockDim.x + threadIdx.x;
    int stride = gridDim.x * blockDim.x;
    for (int j = i; j < 128 * 256; j += stride) {
        int k = j >> 8;          // row (input feature)
        int t = j & 255;         // output col
        g_WT1[j] = (t < 128) ? Ws1[t * 128 + k] : Wn1[(t - 128) * 128 + k];
    }
    for (int j = i; j < 128 * 128; j += stride) {
        int k = j >> 7;
        int t = j & 127;
        g_WT2[j] = (t < 64) ? Ws2[t * 128 + k] : Wn2[(t - 64) * 128 + k];
    }
}

// ---------------------------------------------------------------------------
// Degree (float, matches reference segment_sum of ones)
// ---------------------------------------------------------------------------
__global__ void degree_kernel(const int* __restrict__ dst) {
    int e = blockIdx.x * blockDim.x + threadIdx.x;
    if (e < NEDGES) atomicAdd(&g_DEG[dst[e]], 1.0f);
}

// ---------------------------------------------------------------------------
// GEMM: C[M, NO] = A[M,128] @ WT[128, NO]   (WT is k-major)
// Block: NO/2 threads (one col-pair per thread), R rows per block.
// x rows cached in shared memory in "duplicated pair" layout so LDS.128
// directly yields {x_k, x_k, x_{k+1}, x_{k+1}} for packed f32x2 FMA.
// ---------------------------------------------------------------------------
template <int NO, int R>
__global__ void gemm_kernel(const float* __restrict__ A,
                            const float* __restrict__ WT,
                            float* __restrict__ C, int M) {
    constexpr int NT = NO / 2;
    __shared__ float4 xsd[R * 64];  // per row: 64 float4 (dup-pair layout)

    int t = threadIdx.x;            // col-pair index
    int base = blockIdx.x * R;

    // Cooperative load of R rows of A (float4), write dup pairs
    for (int i = t; i < R * 32; i += NT) {
        int r = i >> 5;
        int q = i & 31;
        float4 v;
        if (base + r < M) v = reinterpret_cast<const float4*>(A)[(base + r) * 32 + q];
        else              v = make_float4(0.f, 0.f, 0.f, 0.f);
        xsd[r * 64 + 2 * q]     = make_float4(v.x, v.x, v.y, v.y);
        xsd[r * 64 + 2 * q + 1] = make_float4(v.z, v.z, v.w, v.w);
    }
    __syncthreads();

    float2 acc[R];
#pragma unroll
    for (int r = 0; r < R; r++) acc[r] = make_float2(0.f, 0.f);

    const float2* WTp = reinterpret_cast<const float2*>(WT);
#pragma unroll 4
    for (int k4 = 0; k4 < 32; k4++) {
        float2 w0 = WTp[(4 * k4 + 0) * NT + t];
        float2 w1 = WTp[(4 * k4 + 1) * NT + t];
        float2 w2 = WTp[(4 * k4 + 2) * NT + t];
        float2 w3 = WTp[(4 * k4 + 3) * NT + t];
#pragma unroll
        for (int r = 0; r < R; r++) {
            float4 xa = xsd[r * 64 + 2 * k4];
            float4 xb = xsd[r * 64 + 2 * k4 + 1];
            acc[r] = ffma2(make_float2(xa.x, xa.y), w0, acc[r]);
            acc[r] = ffma2(make_float2(xa.z, xa.w), w1, acc[r]);
            acc[r] = ffma2(make_float2(xb.x, xb.y), w2, acc[r]);
            acc[r] = ffma2(make_float2(xb.z, xb.w), w3, acc[r]);
        }
    }

#pragma unroll
    for (int r = 0; r < R; r++) {
        if (base + r < M)
            reinterpret_cast<float2*>(C)[(base + r) * NT + t] = acc[r];
    }
}

// ---------------------------------------------------------------------------
// Edge aggregation, layer 1: 128-dim rows, one warp per edge, float4 atomics.
// P1 lives in columns [128,256) of C1 (float4 index 32..63 of each 64-f4 row).
// ---------------------------------------------------------------------------
__global__ void agg128_kernel(const int* __restrict__ src,
                              const int* __restrict__ dst) {
    int gt = blockIdx.x * blockDim.x + threadIdx.x;
    int e = gt >> 5;
    int l = gt & 31;
    if (e >= NEDGES) return;
    int s = __ldg(&src[e]);
    int d = __ldg(&dst[e]);
    float4 v = g_C1[s * 64 + 32 + l];
    atomicAdd(&g_AGG1[d * 32 + l], v);
}

// ---------------------------------------------------------------------------
// Edge aggregation, layer 2: 64-dim rows, 16 lanes per edge.
// P2 lives in columns [64,128) of C2 (float4 index 16..31 of each 32-f4 row).
// ---------------------------------------------------------------------------
__global__ void agg64_kernel(const int* __restrict__ src,
                             const int* __restrict__ dst) {
    int gt = blockIdx.x * blockDim.x + threadIdx.x;
    int e = gt >> 4;
    int l = gt & 15;
    if (e >= NEDGES) return;
    int s = __ldg(&src[e]);
    int d = __ldg(&dst[e]);
    float4 v = g_C2[s * 32 + 16 + l];
    atomicAdd(&g_AGG2[d * 16 + l], v);
}

// ---------------------------------------------------------------------------
// Layer-1 epilogue: h1 = relu(self + agg/max(deg,1) + b1)
// ---------------------------------------------------------------------------
__global__ void finalize1_kernel(const float* __restrict__ b1) {
    int idx = blockIdx.x * blockDim.x + threadIdx.x;  // over N*32 float4s
    if (idx >= NNODES * 32) return;
    int i = idx >> 5;
    int q = idx & 31;
    float rdeg = 1.0f / fmaxf(g_DEG[i], 1.0f);
    float4 s = g_C1[i * 64 + q];           // self half (cols 0..127)
    float4 a = g_AGG1[idx];
    float4 bb = reinterpret_cast<const float4*>(b1)[q];
    float4 h;
    h.x = fmaxf(fmaf(a.x, rdeg, s.x) + bb.x, 0.f);
    h.y = fmaxf(fmaf(a.y, rdeg, s.y) + bb.y, 0.f);
    h.z = fmaxf(fmaf(a.z, rdeg, s.z) + bb.z, 0.f);
    h.w = fmaxf(fmaf(a.w, rdeg, s.w) + bb.w, 0.f);
    g_H1[idx] = h;
}

// ---------------------------------------------------------------------------
// Layer-2 epilogue: out = self + agg/max(deg,1) + b2  (no relu)
// ---------------------------------------------------------------------------
__global__ void finalize2_kernel(const float* __restrict__ b2,
                                 float4* __restrict__ out) {
    int idx = blockIdx.x * blockDim.x + threadIdx.x;  // over N*16 float4s
    if (idx >= NNODES * 16) return;
    int i = idx >> 4;
    int q = idx & 15;
    float rdeg = 1.0f / fmaxf(g_DEG[i], 1.0f);
    float4 s = g_C2[i * 32 + q];           // self half (cols 0..63)
    float4 a = g_AGG2[idx];
    float4 bb = reinterpret_cast<const float4*>(b2)[q];
    float4 o;
    o.x = fmaf(a.x, rdeg, s.x) + bb.x;
    o.y = fmaf(a.y, rdeg, s.y) + bb.y;
    o.z = fmaf(a.z, rdeg, s.z) + bb.z;
    o.w = fmaf(a.w, rdeg, s.w) + bb.w;
    out[idx] = o;
}

// ---------------------------------------------------------------------------
// Launch
// ---------------------------------------------------------------------------
extern "C" void kernel_launch(void* const* d_in, const int* in_sizes, int n_in,
                              void* d_out, int out_size) {
    const float* x   = (const float*)d_in[0];
    const float* Ws1 = (const float*)d_in[1];
    const float* Wn1 = (const float*)d_in[2];
    const float* b1  = (const float*)d_in[3];
    const float* Ws2 = (const float*)d_in[4];
    const float* Wn2 = (const float*)d_in[5];
    const float* b2  = (const float*)d_in[6];
    const int*   src = (const int*)d_in[7];
    const int*   dst = (const int*)d_in[8];
    float4* out = (float4*)d_out;

    float4* agg1 = nullptr; float4* agg2 = nullptr; float4* deg4 = nullptr;
    float*  h1   = nullptr; float*  c1   = nullptr; float*  c2 = nullptr;
    float*  wt1  = nullptr; float*  wt2  = nullptr;
    cudaGetSymbolAddress((void**)&agg1, g_AGG1);
    cudaGetSymbolAddress((void**)&agg2, g_AGG2);
    cudaGetSymbolAddress((void**)&deg4, g_DEG);
    cudaGetSymbolAddress((void**)&h1,  g_H1);
    cudaGetSymbolAddress((void**)&c1,  g_C1);
    cudaGetSymbolAddress((void**)&c2,  g_C2);
    cudaGetSymbolAddress((void**)&wt1, g_WT1);
    cudaGetSymbolAddress((void**)&wt2, g_WT2);

    // Zero accumulators + degrees
    zero4_kernel<<<2048, 256>>>(agg1, NNODES * 32);
    zero4_kernel<<<1024, 256>>>(agg2, NNODES * 16);
    zero4_kernel<<<64,   256>>>(deg4, NNODES / 4);

    // Weight transposes
    prep_weights_kernel<<<64, 256>>>(Ws1, Wn1, Ws2, Wn2);

    // Degrees
    degree_kernel<<<(NEDGES + 255) / 256, 256>>>(dst);

    // Layer 1 combined GEMM: C1 = x @ [Ws1^T | Wn1^T]  (N x 256)
    gemm_kernel<256, 8><<<(NNODES + 7) / 8, 128>>>(x, wt1, c1, NNODES);

    // Layer 1 aggregation (128-dim, warp per edge)
    agg128_kernel<<<(NEDGES * 32 + 255) / 256, 256>>>(src, dst);

    // Layer 1 epilogue
    finalize1_kernel<<<(NNODES * 32 + 255) / 256, 256>>>(b1);

    // Layer 2 combined GEMM: C2 = h1 @ [Ws2^T | Wn2^T]  (N x 128)
    gemm_kernel<128, 8><<<(NNODES + 7) / 8, 64>>>(h1, wt2, c2, NNODES);

    // Layer 2 aggregation (64-dim, 16 lanes per edge)
    agg64_kernel<<<(NEDGES * 16 + 255) / 256, 256>>>(src, dst);

    // Layer 2 epilogue -> output
    finalize2_kernel<<<(NNODES * 16 + 255) / 256, 256>>>(b2, out);
}

// round 2
// speedup vs baseline: 1.2330x; 1.2330x over previous
#include <cuda_runtime.h>
#include <cstdint>

// Problem constants (match reference setup_inputs)
#define NNODES 50000
#define NEDGES 640000
// IN_DIM = 128, HID = 128, OUT = 64

// ---------------------------------------------------------------------------
// Device scratch (allocation-free rule: __device__ globals)
// ---------------------------------------------------------------------------
// Layer-1 combined GEMM output: [N, 256] = [x@Ws1^T | x@Wn1^T]
__device__ float4 g_C1[NNODES * 64];      // 51.2 MB
// Hidden activations after layer 1: [N, 128]
__device__ float4 g_H1[NNODES * 32];      // 25.6 MB
// Layer-2 combined GEMM output: [N, 128] = [h1@Ws2^T | h1@Wn2^T]
__device__ float4 g_C2[NNODES * 32];      // 25.6 MB
// Transposed+concatenated weights
__device__ float  g_WT1[128 * 256];
__device__ float  g_WT2[128 * 128];
// CSR build scratch
__device__ int    g_cnt[NNODES];          // per-dst degree (int)
__device__ int    g_off[NNODES];          // exclusive prefix of g_cnt
__device__ int    g_cur[NNODES];          // scatter cursors
__device__ int    g_csr[NEDGES];          // src ids grouped by dst
__device__ int    g_blkSums[128];         // scan block partials

// ---------------------------------------------------------------------------
// Packed fp32x2 FMA (Blackwell, PTX ISA 8.6+, sm_100+)
// ---------------------------------------------------------------------------
__device__ __forceinline__ float2 ffma2(float2 a, float2 b, float2 c) {
    float2 d;
    asm("{\n\t"
        ".reg .b64 ra, rb, rc, rd;\n\t"
        "mov.b64 ra, {%2, %3};\n\t"
        "mov.b64 rb, {%4, %5};\n\t"
        "mov.b64 rc, {%6, %7};\n\t"
        "fma.rn.f32x2 rd, ra, rb, rc;\n\t"
        "mov.b64 {%0, %1}, rd;\n\t"
        "}"
        : "=f"(d.x), "=f"(d.y)
        : "f"(a.x), "f"(a.y), "f"(b.x), "f"(b.y), "f"(c.x), "f"(c.y));
    return d;
}

__device__ __forceinline__ float4 f4add(float4 a, float4 b) {
    return make_float4(a.x + b.x, a.y + b.y, a.z + b.z, a.w + b.w);
}

// ---------------------------------------------------------------------------
// CSR build: zero counts -> histogram -> 3-phase exclusive scan -> scatter
// ---------------------------------------------------------------------------
__global__ void zero_cnt_kernel() {
    int i = blockIdx.x * blockDim.x + threadIdx.x;
    if (i < NNODES) g_cnt[i] = 0;
}

__global__ void hist_kernel(const int* __restrict__ dst) {
    int e = blockIdx.x * blockDim.x + threadIdx.x;
    if (e < NEDGES) atomicAdd(&g_cnt[dst[e]], 1);
}

// Phase A: per-block (512 nodes) exclusive scan + block totals
__global__ void scanA_kernel() {
    __shared__ int s[512];
    int b = blockIdx.x, t = threadIdx.x;
    int i = b * 512 + t;
    int v = (i < NNODES) ? g_cnt[i] : 0;
    s[t] = v;
    __syncthreads();
#pragma unroll
    for (int d = 1; d < 512; d <<= 1) {
        int x = (t >= d) ? s[t - d] : 0;
        __syncthreads();
        s[t] += x;
        __syncthreads();
    }
    if (i < NNODES) g_off[i] = s[t] - v;   // local exclusive
    if (t == 511) g_blkSums[b] = s[t];     // block total
}

// Phase B: scan the block totals (tiny; single thread)
__global__ void scanB_kernel(int nblocks) {
    if (threadIdx.x == 0 && blockIdx.x == 0) {
        int run = 0;
        for (int i = 0; i < nblocks; i++) {
            int v = g_blkSums[i];
            g_blkSums[i] = run;
            run += v;
        }
    }
}

// Phase C: add block offsets, init cursors
__global__ void scanC_kernel() {
    int i = blockIdx.x * blockDim.x + threadIdx.x;
    if (i < NNODES) {
        int o = g_off[i] + g_blkSums[i >> 9];
        g_off[i] = o;
        g_cur[i] = o;
    }
}

__global__ void scatter_kernel(const int* __restrict__ src,
                               const int* __restrict__ dst) {
    int e = blockIdx.x * blockDim.x + threadIdx.x;
    if (e < NEDGES) {
        int d = dst[e];
        int p = atomicAdd(&g_cur[d], 1);
        g_csr[p] = src[e];
    }
}

// ---------------------------------------------------------------------------
// Build transposed weight matrices in scratch
// ---------------------------------------------------------------------------
__global__ void prep_weights_kernel(const float* __restrict__ Ws1,
                                    const float* __restrict__ Wn1,
                                    const float* __restrict__ Ws2,
                                    const float* __restrict__ Wn2) {
    int i = blockIdx.x * blockDim.x + threadIdx.x;
    int stride = gridDim.x * blockDim.x;
    for (int j = i; j < 128 * 256; j += stride) {
        int k = j >> 8;
        int t = j & 255;
        g_WT1[j] = (t < 128) ? Ws1[t * 128 + k] : Wn1[(t - 128) * 128 + k];
    }
    for (int j = i; j < 128 * 128; j += stride) {
        int k = j >> 7;
        int t = j & 127;
        g_WT2[j] = (t < 64) ? Ws2[t * 128 + k] : Wn2[(t - 64) * 128 + k];
    }
}

// ---------------------------------------------------------------------------
// GEMM: C[M, NO] = A[M,128] @ WT[128, NO]   (WT is k-major)  [unchanged]
// ---------------------------------------------------------------------------
template <int NO, int R>
__global__ void gemm_kernel(const float* __restrict__ A,
                            const float* __restrict__ WT,
                            float* __restrict__ C, int M) {
    constexpr int NT = NO / 2;
    __shared__ float4 xsd[R * 64];

    int t = threadIdx.x;
    int base = blockIdx.x * R;

    for (int i = t; i < R * 32; i += NT) {
        int r = i >> 5;
        int q = i & 31;
        float4 v;
        if (base + r < M) v = reinterpret_cast<const float4*>(A)[(base + r) * 32 + q];
        else              v = make_float4(0.f, 0.f, 0.f, 0.f);
        xsd[r * 64 + 2 * q]     = make_float4(v.x, v.x, v.y, v.y);
        xsd[r * 64 + 2 * q + 1] = make_float4(v.z, v.z, v.w, v.w);
    }
    __syncthreads();

    float2 acc[R];
#pragma unroll
    for (int r = 0; r < R; r++) acc[r] = make_float2(0.f, 0.f);

    const float2* WTp = reinterpret_cast<const float2*>(WT);
#pragma unroll 4
    for (int k4 = 0; k4 < 32; k4++) {
        float2 w0 = WTp[(4 * k4 + 0) * NT + t];
        float2 w1 = WTp[(4 * k4 + 1) * NT + t];
        float2 w2 = WTp[(4 * k4 + 2) * NT + t];
        float2 w3 = WTp[(4 * k4 + 3) * NT + t];
#pragma unroll
        for (int r = 0; r < R; r++) {
            float4 xa = xsd[r * 64 + 2 * k4];
            float4 xb = xsd[r * 64 + 2 * k4 + 1];
            acc[r] = ffma2(make_float2(xa.x, xa.y), w0, acc[r]);
            acc[r] = ffma2(make_float2(xa.z, xa.w), w1, acc[r]);
            acc[r] = ffma2(make_float2(xb.x, xb.y), w2, acc[r]);
            acc[r] = ffma2(make_float2(xb.z, xb.w), w3, acc[r]);
        }
    }

#pragma unroll
    for (int r = 0; r < R; r++) {
        if (base + r < M)
            reinterpret_cast<float2*>(C)[(base + r) * NT + t] = acc[r];
    }
}

// ---------------------------------------------------------------------------
// Fused CSR aggregation + epilogue, layer 1.
// Warp per node: 32 lanes x float4 = 128-float row. 4-way unrolled gather.
// h1 = relu(self + (sum over neigh P1)/max(deg,1) + b1)
// ---------------------------------------------------------------------------
__global__ void agg_fin1_kernel(const float* __restrict__ b1) {
    int warp = (blockIdx.x * blockDim.x + threadIdx.x) >> 5;
    int lane = threadIdx.x & 31;
    if (warp >= NNODES) return;
    int node = warp;

    int beg = g_off[node];
    int cnt = g_cnt[node];
    int end = beg + cnt;

    float4 a0 = make_float4(0.f, 0.f, 0.f, 0.f);
    float4 a1 = a0, a2 = a0, a3 = a0;

    int j = beg;
    for (; j + 4 <= end; j += 4) {
        int s0 = g_csr[j];
        int s1 = g_csr[j + 1];
        int s2 = g_csr[j + 2];
        int s3 = g_csr[j + 3];
        a0 = f4add(a0, g_C1[s0 * 64 + 32 + lane]);
        a1 = f4add(a1, g_C1[s1 * 64 + 32 + lane]);
        a2 = f4add(a2, g_C1[s2 * 64 + 32 + lane]);
        a3 = f4add(a3, g_C1[s3 * 64 + 32 + lane]);
    }
    for (; j < end; j++) {
        int s = g_csr[j];
        a0 = f4add(a0, g_C1[s * 64 + 32 + lane]);
    }
    float4 sum = f4add(f4add(a0, a1), f4add(a2, a3));

    float rdeg = 1.0f / fmaxf((float)cnt, 1.0f);
    float4 self = g_C1[node * 64 + lane];
    float4 bb = reinterpret_cast<const float4*>(b1)[lane];
    float4 h;
    h.x = fmaxf(fmaf(sum.x, rdeg, self.x) + bb.x, 0.f);
    h.y = fmaxf(fmaf(sum.y, rdeg, self.y) + bb.y, 0.f);
    h.z = fmaxf(fmaf(sum.z, rdeg, self.z) + bb.z, 0.f);
    h.w = fmaxf(fmaf(sum.w, rdeg, self.w) + bb.w, 0.f);
    g_H1[node * 32 + lane] = h;
}

// ---------------------------------------------------------------------------
// Fused CSR aggregation + epilogue, layer 2.
// 16-lane group per node: 16 x float4 = 64-float row.
// out = self + (sum over neigh P2)/max(deg,1) + b2  (no relu)
// ---------------------------------------------------------------------------
__global__ void agg_fin2_kernel(const float* __restrict__ b2,
                                float4* __restrict__ out) {
    int grp = (blockIdx.x * blockDim.x + threadIdx.x) >> 4;
    int lane = threadIdx.x & 15;
    if (grp >= NNODES) return;
    int node = grp;

    int beg = g_off[node];
    int cnt = g_cnt[node];
    int end = beg + cnt;

    float4 a0 = make_float4(0.f, 0.f, 0.f, 0.f);
    float4 a1 = a0, a2 = a0, a3 = a0;

    int j = beg;
    for (; j + 4 <= end; j += 4) {
        int s0 = g_csr[j];
        int s1 = g_csr[j + 1];
        int s2 = g_csr[j + 2];
        int s3 = g_csr[j + 3];
        a0 = f4add(a0, g_C2[s0 * 32 + 16 + lane]);
        a1 = f4add(a1, g_C2[s1 * 32 + 16 + lane]);
        a2 = f4add(a2, g_C2[s2 * 32 + 16 + lane]);
        a3 = f4add(a3, g_C2[s3 * 32 + 16 + lane]);
    }
    for (; j < end; j++) {
        int s = g_csr[j];
        a0 = f4add(a0, g_C2[s * 32 + 16 + lane]);
    }
    float4 sum = f4add(f4add(a0, a1), f4add(a2, a3));

    float rdeg = 1.0f / fmaxf((float)cnt, 1.0f);
    float4 self = g_C2[node * 32 + lane];
    float4 bb = reinterpret_cast<const float4*>(b2)[lane];
    float4 o;
    o.x = fmaf(sum.x, rdeg, self.x) + bb.x;
    o.y = fmaf(sum.y, rdeg, self.y) + bb.y;
    o.z = fmaf(sum.z, rdeg, self.z) + bb.z;
    o.w = fmaf(sum.w, rdeg, self.w) + bb.w;
    out[node * 16 + lane] = o;
}

// ---------------------------------------------------------------------------
// Launch
// ---------------------------------------------------------------------------
extern "C" void kernel_launch(void* const* d_in, const int* in_sizes, int n_in,
                              void* d_out, int out_size) {
    const float* x   = (const float*)d_in[0];
    const float* Ws1 = (const float*)d_in[1];
    const float* Wn1 = (const float*)d_in[2];
    const float* b1  = (const float*)d_in[3];
    const float* Ws2 = (const float*)d_in[4];
    const float* Wn2 = (const float*)d_in[5];
    const float* b2  = (const float*)d_in[6];
    const int*   src = (const int*)d_in[7];
    const int*   dst = (const int*)d_in[8];
    float4* out = (float4*)d_out;

    float* h1 = nullptr; float* c1 = nullptr; float* c2 = nullptr;
    float* wt1 = nullptr; float* wt2 = nullptr;
    cudaGetSymbolAddress((void**)&h1,  g_H1);
    cudaGetSymbolAddress((void**)&c1,  g_C1);
    cudaGetSymbolAddress((void**)&c2,  g_C2);
    cudaGetSymbolAddress((void**)&wt1, g_WT1);
    cudaGetSymbolAddress((void**)&wt2, g_WT2);

    const int SCAN_BLOCKS = (NNODES + 511) / 512;   // 98

    // CSR build
    zero_cnt_kernel<<<(NNODES + 255) / 256, 256>>>();
    hist_kernel<<<(NEDGES + 255) / 256, 256>>>(dst);
    scanA_kernel<<<SCAN_BLOCKS, 512>>>();
    scanB_kernel<<<1, 32>>>(SCAN_BLOCKS);
    scanC_kernel<<<(NNODES + 255) / 256, 256>>>();
    scatter_kernel<<<(NEDGES + 255) / 256, 256>>>(src, dst);

    // Weight transposes
    prep_weights_kernel<<<64, 256>>>(Ws1, Wn1, Ws2, Wn2);

    // Layer 1: GEMM then fused aggregation+epilogue
    gemm_kernel<256, 8><<<(NNODES + 7) / 8, 128>>>(x, wt1, c1, NNODES);
    agg_fin1_kernel<<<(NNODES * 32 + 255) / 256, 256>>>(b1);

    // Layer 2: GEMM then fused aggregation+epilogue -> output
    gemm_kernel<128, 8><<<(NNODES + 7) / 8, 64>>>(h1, wt2, c2, NNODES);
    agg_fin2_kernel<<<(NNODES * 16 + 255) / 256, 256>>>(b2, out);
}

// round 4
// speedup vs baseline: 1.6896x; 1.3703x over previous
#include <cuda_runtime.h>
#include <cuda_bf16.h>
#include <cstdint>

// Problem constants (match reference setup_inputs)
#define NNODES 50000
#define NEDGES 640000
// IN_DIM = 128, HID = 128, OUT = 64

// ---------------------------------------------------------------------------
// Device scratch (allocation-free rule: __device__ globals)
// ---------------------------------------------------------------------------
__device__ float4 g_C1[NNODES * 64];      // [N,256] = [x@Ws1^T | x@Wn1^T]
__device__ float4 g_H1[NNODES * 32];      // [N,128] hidden
__device__ float4 g_C2[NNODES * 32];      // [N,128] = [h1@Ws2^T | h1@Wn2^T]
// bf16 hi/lo split weights, plain [n][k] row-major (k contiguous)
__device__ __align__(16) __nv_bfloat16 g_W1H[256 * 128];
__device__ __align__(16) __nv_bfloat16 g_W1L[256 * 128];
__device__ __align__(16) __nv_bfloat16 g_W2H[128 * 128];
__device__ __align__(16) __nv_bfloat16 g_W2L[128 * 128];
// CSR build scratch
__device__ int    g_cnt[NNODES];
__device__ int    g_off[NNODES];
__device__ int    g_cur[NNODES];
__device__ int    g_csr[NEDGES];
__device__ int    g_blkSums[128];

// ---------------------------------------------------------------------------
// Helpers
// ---------------------------------------------------------------------------
__device__ __forceinline__ uint32_t smem_u32(const void* p) {
    uint32_t a;
    asm("{ .reg .u64 t; cvta.to.shared.u64 t, %1; cvt.u32.u64 %0, t; }"
        : "=r"(a) : "l"(p));
    return a;
}
__device__ __forceinline__ void ldsm4(uint32_t* r, uint32_t addr) {
    asm volatile("ldmatrix.sync.aligned.m8n8.x4.shared.b16 {%0,%1,%2,%3}, [%4];"
                 : "=r"(r[0]), "=r"(r[1]), "=r"(r[2]), "=r"(r[3]) : "r"(addr));
}
__device__ __forceinline__ void mma_bf16(float* d, const uint32_t* a,
                                         uint32_t b0, uint32_t b1) {
    asm volatile(
        "mma.sync.aligned.m16n8k16.row.col.f32.bf16.bf16.f32 "
        "{%0,%1,%2,%3}, {%4,%5,%6,%7}, {%8,%9}, {%0,%1,%2,%3};"
        : "+f"(d[0]), "+f"(d[1]), "+f"(d[2]), "+f"(d[3])
        : "r"(a[0]), "r"(a[1]), "r"(a[2]), "r"(a[3]), "r"(b0), "r"(b1));
}
__device__ __forceinline__ float4 f4add(float4 a, float4 b) {
    return make_float4(a.x + b.x, a.y + b.y, a.z + b.z, a.w + b.w);
}

// ---------------------------------------------------------------------------
// CSR build: zero counts -> histogram -> 3-phase exclusive scan -> scatter
// ---------------------------------------------------------------------------
__global__ void zero_cnt_kernel() {
    int i = blockIdx.x * blockDim.x + threadIdx.x;
    if (i < NNODES) g_cnt[i] = 0;
}
__global__ void hist_kernel(const int* __restrict__ dst) {
    int e = blockIdx.x * blockDim.x + threadIdx.x;
    if (e < NEDGES) atomicAdd(&g_cnt[dst[e]], 1);
}
__global__ void scanA_kernel() {
    __shared__ int s[512];
    int b = blockIdx.x, t = threadIdx.x;
    int i = b * 512 + t;
    int v = (i < NNODES) ? g_cnt[i] : 0;
    s[t] = v;
    __syncthreads();
#pragma unroll
    for (int d = 1; d < 512; d <<= 1) {
        int x = (t >= d) ? s[t - d] : 0;
        __syncthreads();
        s[t] += x;
        __syncthreads();
    }
    if (i < NNODES) g_off[i] = s[t] - v;
    if (t == 511) g_blkSums[b] = s[t];
}
__global__ void scanB_kernel(int nblocks) {
    __shared__ int s[128];
    int t = threadIdx.x;
    int v = (t < nblocks) ? g_blkSums[t] : 0;
    s[t] = v;
    __syncthreads();
#pragma unroll
    for (int d = 1; d < 128; d <<= 1) {
        int x = (t >= d) ? s[t - d] : 0;
        __syncthreads();
        s[t] += x;
        __syncthreads();
    }
    if (t < nblocks) g_blkSums[t] = s[t] - v;
}
__global__ void scanC_kernel() {
    int i = blockIdx.x * blockDim.x + threadIdx.x;
    if (i < NNODES) {
        int o = g_off[i] + g_blkSums[i >> 9];
        g_off[i] = o;
        g_cur[i] = o;
    }
}
__global__ void scatter_kernel(const int* __restrict__ src,
                               const int* __restrict__ dst) {
    int e = blockIdx.x * blockDim.x + threadIdx.x;
    if (e < NEDGES) {
        int d = dst[e];
        int p = atomicAdd(&g_cur[d], 1);
        g_csr[p] = src[e];
    }
}

// ---------------------------------------------------------------------------
// Weight prep: split fp32 -> bf16 hi/lo, plain [n][k] layout.
// Concatenated rows: layer1 n<128: Ws1, n>=128: Wn1; layer2 n<64: Ws2, else Wn2.
// ---------------------------------------------------------------------------
__global__ void prep_w_kernel(const float* __restrict__ Ws1,
                              const float* __restrict__ Wn1,
                              const float* __restrict__ Ws2,
                              const float* __restrict__ Wn2) {
    int i = blockIdx.x * blockDim.x + threadIdx.x;
    if (i < 256 * 128) {
        int n = i >> 7, k = i & 127;
        float w = (n < 128) ? Ws1[n * 128 + k] : Wn1[(n - 128) * 128 + k];
        __nv_bfloat16 h = __float2bfloat16_rn(w);
        g_W1H[i] = h;
        g_W1L[i] = __float2bfloat16_rn(w - __bfloat162float(h));
    }
    if (i < 128 * 128) {
        int n = i >> 7, k = i & 127;
        float w = (n < 64) ? Ws2[n * 128 + k] : Wn2[(n - 64) * 128 + k];
        __nv_bfloat16 h = __float2bfloat16_rn(w);
        g_W2H[i] = h;
        g_W2L[i] = __float2bfloat16_rn(w - __bfloat162float(h));
    }
}

// ---------------------------------------------------------------------------
// Tensor-core GEMM via mma.sync (HMMA), split-bf16 (3 terms, fp32 accum).
// C[64-row tile, NOUT] = A[.,128] @ Wcat^T
// CTA = 128 threads (4 warps). Warp tile = 32 rows x 64 cols.
//   warp: rg = warp>>1 (row group of 32), cg = warp&1 (col group of 64)
// SMEM (dynamic): AH[64][136] AL[64][136] WH[128][136] WL[128][136] bf16
// Stride 136 bf16 (272B) => ldmatrix conflict-free (68 words = 4 mod 32).
// ---------------------------------------------------------------------------
template <int NOUT>
__global__ void __launch_bounds__(128)
gemm_mma_kernel(const float* __restrict__ A,
                const __nv_bfloat16* __restrict__ WHg,
                const __nv_bfloat16* __restrict__ WLg,
                float* __restrict__ C, int M) {
    constexpr int ASTR = 136;
    constexpr int WSTR = 136;
    extern __shared__ __nv_bfloat16 smem[];
    __nv_bfloat16* sAH = smem;                    // 64*136
    __nv_bfloat16* sAL = sAH + 64 * ASTR;
    __nv_bfloat16* sWH = sAL + 64 * ASTR;         // 128*136
    __nv_bfloat16* sWL = sWH + 128 * WSTR;

    int tid = threadIdx.x;
    int warp = tid >> 5, lane = tid & 31;
    int rg = warp >> 1, cg = warp & 1;
    int base = blockIdx.x * 64;

    // ---- Load A tile (64 rows x 128 fp32), split to bf16 hi/lo in SMEM ----
    {
        int row = tid >> 1;
        int cbase = (tid & 1) * 64;
        int grow = base + row;
        const float4* A4 = reinterpret_cast<const float4*>(A);
#pragma unroll
        for (int i = 0; i < 8; i++) {
            float4 u, v;
            if (grow < M) {
                u = A4[(size_t)grow * 32 + (cbase >> 2) + 2 * i];
                v = A4[(size_t)grow * 32 + (cbase >> 2) + 2 * i + 1];
            } else {
                u = v = make_float4(0.f, 0.f, 0.f, 0.f);
            }
            float f[8] = {u.x, u.y, u.z, u.w, v.x, v.y, v.z, v.w};
            alignas(16) __nv_bfloat16 hb[8], lb[8];
#pragma unroll
            for (int q = 0; q < 8; q++) {
                __nv_bfloat16 h = __float2bfloat16_rn(f[q]);
                hb[q] = h;
                lb[q] = __float2bfloat16_rn(f[q] - __bfloat162float(h));
            }
            int off = row * ASTR + cbase + 8 * i;
            *reinterpret_cast<uint4*>(sAH + off) = *reinterpret_cast<uint4*>(hb);
            *reinterpret_cast<uint4*>(sAL + off) = *reinterpret_cast<uint4*>(lb);
        }
    }

    // Per-thread ldmatrix base offsets
    int g8 = lane >> 3, j8 = lane & 7;
    // A: row = rg*32 + mb*16 + (g8&1)*8 + j8 ; k = (g8>>1)*8
    uint32_t aA0 = smem_u32(sAH) +
                   (uint32_t)(((rg * 32 + (g8 & 1) * 8 + j8) * ASTR + (g8 >> 1) * 8) * 2);
    constexpr uint32_t A_MB   = 16u * ASTR * 2u;       // m-block stride
    constexpr uint32_t A_LO   = 64u * ASTR * 2u;       // hi->lo plane
    // B: n = cg*64 + np*16 + (g8>>1)*8 + j8 ; k = (g8&1)*8
    uint32_t aB0 = smem_u32(sWH) +
                   (uint32_t)(((cg * 64 + (g8 >> 1) * 8 + j8) * WSTR + (g8 & 1) * 8) * 2);
    constexpr uint32_t B_NP   = 16u * WSTR * 2u;       // nblk-pair stride
    constexpr uint32_t B_LO   = 128u * WSTR * 2u;      // hi->lo plane

#pragma unroll
    for (int h = 0; h < NOUT / 128; h++) {
        // Guard SMEM reuse (A stores for h=0; W reads of previous half after)
        __syncthreads();
        // ---- Load W strip (128 cols x 128 k) hi/lo ----
        {
            int n = tid;
            const uint4* gh = reinterpret_cast<const uint4*>(WHg) + (h * 128 + n) * 16;
            const uint4* gl = reinterpret_cast<const uint4*>(WLg) + (h * 128 + n) * 16;
            uint4* sh = reinterpret_cast<uint4*>(sWH + n * WSTR);
            uint4* sl = reinterpret_cast<uint4*>(sWL + n * WSTR);
#pragma unroll
            for (int i = 0; i < 16; i++) {
                sh[i] = gh[i];
                sl[i] = gl[i];
            }
        }
        __syncthreads();

        float acc[64];
#pragma unroll
        for (int i = 0; i < 64; i++) acc[i] = 0.f;

#pragma unroll
        for (int ks = 0; ks < 8; ks++) {
            uint32_t kb = (uint32_t)(ks * 32);
            uint32_t ah0[4], al0[4], ah1[4], al1[4];
            ldsm4(ah0, aA0 + kb);
            ldsm4(al0, aA0 + A_LO + kb);
            ldsm4(ah1, aA0 + A_MB + kb);
            ldsm4(al1, aA0 + A_MB + A_LO + kb);
#pragma unroll
            for (int np = 0; np < 4; np++) {
                uint32_t bh[4], bl[4];
                ldsm4(bh, aB0 + np * B_NP + kb);
                ldsm4(bl, aB0 + B_LO + np * B_NP + kb);
                // nblk = np*2 (+0: regs b[0],b[1]; +1: b[2],b[3])
                float* d00 = acc + (0 * 8 + np * 2) * 4;
                float* d01 = acc + (0 * 8 + np * 2 + 1) * 4;
                float* d10 = acc + (1 * 8 + np * 2) * 4;
                float* d11 = acc + (1 * 8 + np * 2 + 1) * 4;
                mma_bf16(d00, ah0, bh[0], bh[1]);
                mma_bf16(d00, ah0, bl[0], bl[1]);
                mma_bf16(d00, al0, bh[0], bh[1]);
                mma_bf16(d01, ah0, bh[2], bh[3]);
                mma_bf16(d01, ah0, bl[2], bl[3]);
                mma_bf16(d01, al0, bh[2], bh[3]);
                mma_bf16(d10, ah1, bh[0], bh[1]);
                mma_bf16(d10, ah1, bl[0], bl[1]);
                mma_bf16(d10, al1, bh[0], bh[1]);
                mma_bf16(d11, ah1, bh[2], bh[3]);
                mma_bf16(d11, ah1, bl[2], bl[3]);
                mma_bf16(d11, al1, bh[2], bh[3]);
            }
        }

        // ---- Flush: warp tile rows rg*32+mb*16+{r, r+8}, cols h*128+cg*64+nb*8 ----
        int rq = lane >> 2;
        int cq = 2 * (lane & 3);
#pragma unroll
        for (int mb = 0; mb < 2; mb++) {
#pragma unroll
            for (int nb = 0; nb < 8; nb++) {
                float* d = acc + (mb * 8 + nb) * 4;
                int r0 = base + rg * 32 + mb * 16 + rq;
                int col = h * 128 + cg * 64 + nb * 8 + cq;
                if (r0 < M)
                    *reinterpret_cast<float2*>(&C[(size_t)r0 * NOUT + col]) =
                        make_float2(d[0], d[1]);
                if (r0 + 8 < M)
                    *reinterpret_cast<float2*>(&C[(size_t)(r0 + 8) * NOUT + col]) =
                        make_float2(d[2], d[3]);
            }
        }
    }
}

// ---------------------------------------------------------------------------
// Fused CSR aggregation + epilogue, layer 1 (unchanged from round 2).
// ---------------------------------------------------------------------------
__global__ void agg_fin1_kernel(const float* __restrict__ b1) {
    int warp = (blockIdx.x * blockDim.x + threadIdx.x) >> 5;
    int lane = threadIdx.x & 31;
    if (warp >= NNODES) return;
    int node = warp;

    int beg = g_off[node];
    int cnt = g_cnt[node];
    int end = beg + cnt;

    float4 a0 = make_float4(0.f, 0.f, 0.f, 0.f);
    float4 a1 = a0, a2 = a0, a3 = a0;

    int j = beg;
    for (; j + 4 <= end; j += 4) {
        int s0 = g_csr[j];
        int s1 = g_csr[j + 1];
        int s2 = g_csr[j + 2];
        int s3 = g_csr[j + 3];
        a0 = f4add(a0, g_C1[s0 * 64 + 32 + lane]);
        a1 = f4add(a1, g_C1[s1 * 64 + 32 + lane]);
        a2 = f4add(a2, g_C1[s2 * 64 + 32 + lane]);
        a3 = f4add(a3, g_C1[s3 * 64 + 32 + lane]);
    }
    for (; j < end; j++) {
        int s = g_csr[j];
        a0 = f4add(a0, g_C1[s * 64 + 32 + lane]);
    }
    float4 sum = f4add(f4add(a0, a1), f4add(a2, a3));

    float rdeg = 1.0f / fmaxf((float)cnt, 1.0f);
    float4 self = g_C1[node * 64 + lane];
    float4 bb = reinterpret_cast<const float4*>(b1)[lane];
    float4 h;
    h.x = fmaxf(fmaf(sum.x, rdeg, self.x) + bb.x, 0.f);
    h.y = fmaxf(fmaf(sum.y, rdeg, self.y) + bb.y, 0.f);
    h.z = fmaxf(fmaf(sum.z, rdeg, self.z) + bb.z, 0.f);
    h.w = fmaxf(fmaf(sum.w, rdeg, self.w) + bb.w, 0.f);
    g_H1[node * 32 + lane] = h;
}

// ---------------------------------------------------------------------------
// Fused CSR aggregation + epilogue, layer 2 (unchanged from round 2).
// ---------------------------------------------------------------------------
__global__ void agg_fin2_kernel(const float* __restrict__ b2,
                                float4* __restrict__ out) {
    int grp = (blockIdx.x * blockDim.x + threadIdx.x) >> 4;
    int lane = threadIdx.x & 15;
    if (grp >= NNODES) return;
    int node = grp;

    int beg = g_off[node];
    int cnt = g_cnt[node];
    int end = beg + cnt;

    float4 a0 = make_float4(0.f, 0.f, 0.f, 0.f);
    float4 a1 = a0, a2 = a0, a3 = a0;

    int j = beg;
    for (; j + 4 <= end; j += 4) {
        int s0 = g_csr[j];
        int s1 = g_csr[j + 1];
        int s2 = g_csr[j + 2];
        int s3 = g_csr[j + 3];
        a0 = f4add(a0, g_C2[s0 * 32 + 16 + lane]);
        a1 = f4add(a1, g_C2[s1 * 32 + 16 + lane]);
        a2 = f4add(a2, g_C2[s2 * 32 + 16 + lane]);
        a3 = f4add(a3, g_C2[s3 * 32 + 16 + lane]);
    }
    for (; j < end; j++) {
        int s = g_csr[j];
        a0 = f4add(a0, g_C2[s * 32 + 16 + lane]);
    }
    float4 sum = f4add(f4add(a0, a1), f4add(a2, a3));

    float rdeg = 1.0f / fmaxf((float)cnt, 1.0f);
    float4 self = g_C2[node * 32 + lane];
    float4 bb = reinterpret_cast<const float4*>(b2)[lane];
    float4 o;
    o.x = fmaf(sum.x, rdeg, self.x) + bb.x;
    o.y = fmaf(sum.y, rdeg, self.y) + bb.y;
    o.z = fmaf(sum.z, rdeg, self.z) + bb.z;
    o.w = fmaf(sum.w, rdeg, self.w) + bb.w;
    out[node * 16 + lane] = o;
}

// ---------------------------------------------------------------------------
// Launch
// ---------------------------------------------------------------------------
extern "C" void kernel_launch(void* const* d_in, const int* in_sizes, int n_in,
                              void* d_out, int out_size) {
    const float* x   = (const float*)d_in[0];
    const float* Ws1 = (const float*)d_in[1];
    const float* Wn1 = (const float*)d_in[2];
    const float* b1  = (const float*)d_in[3];
    const float* Ws2 = (const float*)d_in[4];
    const float* Wn2 = (const float*)d_in[5];
    const float* b2  = (const float*)d_in[6];
    const int*   src = (const int*)d_in[7];
    const int*   dst = (const int*)d_in[8];
    float4* out = (float4*)d_out;

    float* h1 = nullptr; float* c1 = nullptr; float* c2 = nullptr;
    __nv_bfloat16 *w1h = nullptr, *w1l = nullptr, *w2h = nullptr, *w2l = nullptr;
    cudaGetSymbolAddress((void**)&h1,  g_H1);
    cudaGetSymbolAddress((void**)&c1,  g_C1);
    cudaGetSymbolAddress((void**)&c2,  g_C2);
    cudaGetSymbolAddress((void**)&w1h, g_W1H);
    cudaGetSymbolAddress((void**)&w1l, g_W1L);
    cudaGetSymbolAddress((void**)&w2h, g_W2H);
    cudaGetSymbolAddress((void**)&w2l, g_W2L);

    const int SCAN_BLOCKS = (NNODES + 511) / 512;            // 98
    const int GTILES = (NNODES + 63) / 64;                   // 782
    const int GSMEM = (64 * 136 * 2 + 128 * 136 * 2) * 2;    // 104448 bytes

    cudaFuncSetAttribute(gemm_mma_kernel<256>,
                         cudaFuncAttributeMaxDynamicSharedMemorySize, GSMEM);
    cudaFuncSetAttribute(gemm_mma_kernel<128>,
                         cudaFuncAttributeMaxDynamicSharedMemorySize, GSMEM);

    // CSR build
    zero_cnt_kernel<<<(NNODES + 255) / 256, 256>>>();
    hist_kernel<<<(NEDGES + 255) / 256, 256>>>(dst);
    scanA_kernel<<<SCAN_BLOCKS, 512>>>();
    scanB_kernel<<<1, 128>>>(SCAN_BLOCKS);
    scanC_kernel<<<(NNODES + 255) / 256, 256>>>();
    scatter_kernel<<<(NEDGES + 255) / 256, 256>>>(src, dst);

    // Weight prep (bf16 hi/lo split)
    prep_w_kernel<<<128, 256>>>(Ws1, Wn1, Ws2, Wn2);

    // Layer 1: HMMA GEMM then fused aggregation+epilogue
    gemm_mma_kernel<256><<<GTILES, 128, GSMEM>>>(x, w1h, w1l, c1, NNODES);
    agg_fin1_kernel<<<(NNODES * 32 + 255) / 256, 256>>>(b1);

    // Layer 2: HMMA GEMM then fused aggregation+epilogue -> output
    gemm_mma_kernel<128><<<GTILES, 128, GSMEM>>>(h1, w2h, w2l, c2, NNODES);
    agg_fin2_kernel<<<(NNODES * 16 + 255) / 256, 256>>>(b2, out);
}

// round 5
// speedup vs baseline: 2.0510x; 1.2139x over previous
#include <cuda_runtime.h>
#include <cuda_bf16.h>
#include <cstdint>

// Problem constants (match reference setup_inputs)
#define NNODES 50000
#define NEDGES 640000
// IN_DIM = 128, HID = 128, OUT = 64

// ---------------------------------------------------------------------------
// Device scratch (allocation-free rule: __device__ globals)
// ---------------------------------------------------------------------------
__device__ float4 g_C1[NNODES * 64];      // [N,256] = [x@Ws1^T | x@Wn1^T]
__device__ float4 g_H1[NNODES * 32];      // [N,128] hidden
__device__ float4 g_C2[NNODES * 32];      // [N,128] = [h1@Ws2^T | h1@Wn2^T]
// bf16 hi/lo split weights, plain [n][k] row-major (k contiguous)
__device__ __align__(16) __nv_bfloat16 g_W1H[256 * 128];
__device__ __align__(16) __nv_bfloat16 g_W1L[256 * 128];
__device__ __align__(16) __nv_bfloat16 g_W2H[128 * 128];
__device__ __align__(16) __nv_bfloat16 g_W2L[128 * 128];
// CSR build scratch
__device__ int    g_cnt[NNODES];
__device__ int    g_off[NNODES];
__device__ int    g_cur[NNODES];
__device__ int    g_csr[NEDGES];
__device__ int    g_blkSums[128];

// ---------------------------------------------------------------------------
// Helpers
// ---------------------------------------------------------------------------
__device__ __forceinline__ uint32_t smem_u32(const void* p) {
    uint32_t a;
    asm("{ .reg .u64 t; cvta.to.shared.u64 t, %1; cvt.u32.u64 %0, t; }"
        : "=r"(a) : "l"(p));
    return a;
}
__device__ __forceinline__ void ldsm4(uint32_t* r, uint32_t addr) {
    asm volatile("ldmatrix.sync.aligned.m8n8.x4.shared.b16 {%0,%1,%2,%3}, [%4];"
                 : "=r"(r[0]), "=r"(r[1]), "=r"(r[2]), "=r"(r[3]) : "r"(addr));
}
__device__ __forceinline__ void mma_bf16(float* d, const uint32_t* a,
                                         uint32_t b0, uint32_t b1) {
    asm volatile(
        "mma.sync.aligned.m16n8k16.row.col.f32.bf16.bf16.f32 "
        "{%0,%1,%2,%3}, {%4,%5,%6,%7}, {%8,%9}, {%0,%1,%2,%3};"
        : "+f"(d[0]), "+f"(d[1]), "+f"(d[2]), "+f"(d[3])
        : "r"(a[0]), "r"(a[1]), "r"(a[2]), "r"(a[3]), "r"(b0), "r"(b1));
}
__device__ __forceinline__ float4 f4add(float4 a, float4 b) {
    return make_float4(a.x + b.x, a.y + b.y, a.z + b.z, a.w + b.w);
}

// ---------------------------------------------------------------------------
// CSR build: zero counts -> histogram -> scanA -> scanC(+block prefix) -> scatter
// ---------------------------------------------------------------------------
__global__ void zero_cnt_kernel() {
    int i = blockIdx.x * blockDim.x + threadIdx.x;
    if (i < NNODES) g_cnt[i] = 0;
}
__global__ void hist_kernel(const int* __restrict__ dst) {
    int e = blockIdx.x * blockDim.x + threadIdx.x;
    if (e < NEDGES) atomicAdd(&g_cnt[dst[e]], 1);
}
__global__ void scanA_kernel() {
    __shared__ int s[512];
    int b = blockIdx.x, t = threadIdx.x;
    int i = b * 512 + t;
    int v = (i < NNODES) ? g_cnt[i] : 0;
    s[t] = v;
    __syncthreads();
#pragma unroll
    for (int d = 1; d < 512; d <<= 1) {
        int x = (t >= d) ? s[t - d] : 0;
        __syncthreads();
        s[t] += x;
        __syncthreads();
    }
    if (i < NNODES) g_off[i] = s[t] - v;
    if (t == 511) g_blkSums[b] = s[t];
}
// scanC with inlined block-offset prefix (replaces the old scanB grid-1 kernel)
__global__ void scanC_kernel(int nblocks) {
    __shared__ int s[128];
    int t = threadIdx.x;
    if (t < nblocks) s[t] = g_blkSums[t];
    __syncthreads();
    int i = blockIdx.x * blockDim.x + t;
    if (i < NNODES) {
        int blk = i >> 9;
        int pre = 0;
        for (int j = 0; j < blk; j++) pre += s[j];
        int o = g_off[i] + pre;
        g_off[i] = o;
        g_cur[i] = o;
    }
}
__global__ void scatter_kernel(const int* __restrict__ src,
                               const int* __restrict__ dst) {
    int e = blockIdx.x * blockDim.x + threadIdx.x;
    if (e < NEDGES) {
        int d = dst[e];
        int p = atomicAdd(&g_cur[d], 1);
        g_csr[p] = src[e];
    }
}

// ---------------------------------------------------------------------------
// Weight prep: split fp32 -> bf16 hi/lo, plain [n][k] layout.
// ---------------------------------------------------------------------------
__global__ void prep_w_kernel(const float* __restrict__ Ws1,
                              const float* __restrict__ Wn1,
                              const float* __restrict__ Ws2,
                              const float* __restrict__ Wn2) {
    int i = blockIdx.x * blockDim.x + threadIdx.x;
    if (i < 256 * 128) {
        int n = i >> 7, k = i & 127;
        float w = (n < 128) ? Ws1[n * 128 + k] : Wn1[(n - 128) * 128 + k];
        __nv_bfloat16 h = __float2bfloat16_rn(w);
        g_W1H[i] = h;
        g_W1L[i] = __float2bfloat16_rn(w - __bfloat162float(h));
    }
    if (i < 128 * 128) {
        int n = i >> 7, k = i & 127;
        float w = (n < 64) ? Ws2[n * 128 + k] : Wn2[(n - 64) * 128 + k];
        __nv_bfloat16 h = __float2bfloat16_rn(w);
        g_W2H[i] = h;
        g_W2L[i] = __float2bfloat16_rn(w - __bfloat162float(h));
    }
}

// ---------------------------------------------------------------------------
// Tensor-core GEMM via mma.sync (HMMA), split-bf16 (3 terms, fp32 accum).
// C[128-row tile, NOUT] = A[.,128] @ Wcat^T
// CTA = 256 threads (8 warps). Warp tile = 32 rows x 64 cols:
//   rg = warp>>1 (0..3, row group of 32), cg = warp&1 (col group of 64)
// SMEM: AH[128][136] AL[128][136] WH[128][136] WL[128][136] bf16 (139 KB)
// ---------------------------------------------------------------------------
template <int NOUT>
__global__ void __launch_bounds__(256)
gemm_mma_kernel(const float* __restrict__ A,
                const __nv_bfloat16* __restrict__ WHg,
                const __nv_bfloat16* __restrict__ WLg,
                float* __restrict__ C, int M) {
    constexpr int ASTR = 136;
    constexpr int WSTR = 136;
    extern __shared__ __nv_bfloat16 smem[];
    __nv_bfloat16* sAH = smem;                    // 128*136
    __nv_bfloat16* sAL = sAH + 128 * ASTR;
    __nv_bfloat16* sWH = sAL + 128 * ASTR;        // 128*136
    __nv_bfloat16* sWL = sWH + 128 * WSTR;

    int tid = threadIdx.x;
    int warp = tid >> 5, lane = tid & 31;
    int rg = warp >> 1, cg = warp & 1;
    int base = blockIdx.x * 128;

    // ---- Load A tile (128 rows x 128 fp32), split to bf16 hi/lo in SMEM ----
    {
        int row = tid >> 1;
        int cbase = (tid & 1) * 64;
        int grow = base + row;
        const float4* A4 = reinterpret_cast<const float4*>(A);
#pragma unroll
        for (int i = 0; i < 8; i++) {
            float4 u, v;
            if (grow < M) {
                u = A4[(size_t)grow * 32 + (cbase >> 2) + 2 * i];
                v = A4[(size_t)grow * 32 + (cbase >> 2) + 2 * i + 1];
            } else {
                u = v = make_float4(0.f, 0.f, 0.f, 0.f);
            }
            float f[8] = {u.x, u.y, u.z, u.w, v.x, v.y, v.z, v.w};
            alignas(16) __nv_bfloat16 hb[8], lb[8];
#pragma unroll
            for (int q = 0; q < 8; q++) {
                __nv_bfloat16 h = __float2bfloat16_rn(f[q]);
                hb[q] = h;
                lb[q] = __float2bfloat16_rn(f[q] - __bfloat162float(h));
            }
            int off = row * ASTR + cbase + 8 * i;
            *reinterpret_cast<uint4*>(sAH + off) = *reinterpret_cast<uint4*>(hb);
            *reinterpret_cast<uint4*>(sAL + off) = *reinterpret_cast<uint4*>(lb);
        }
    }

    // Per-thread ldmatrix base offsets
    int g8 = lane >> 3, j8 = lane & 7;
    // A: row = rg*32 + mb*16 + (g8&1)*8 + j8 ; k = (g8>>1)*8
    uint32_t aA0 = smem_u32(sAH) +
                   (uint32_t)(((rg * 32 + (g8 & 1) * 8 + j8) * ASTR + (g8 >> 1) * 8) * 2);
    constexpr uint32_t A_MB = 16u * ASTR * 2u;        // m-block stride
    constexpr uint32_t A_LO = 128u * ASTR * 2u;       // hi->lo plane
    // B: n = cg*64 + np*16 + (g8>>1)*8 + j8 ; k = (g8&1)*8
    uint32_t aB0 = smem_u32(sWH) +
                   (uint32_t)(((cg * 64 + (g8 >> 1) * 8 + j8) * WSTR + (g8 & 1) * 8) * 2);
    constexpr uint32_t B_NP = 16u * WSTR * 2u;        // nblk-pair stride
    constexpr uint32_t B_LO = 128u * WSTR * 2u;       // hi->lo plane

#pragma unroll
    for (int h = 0; h < NOUT / 128; h++) {
        // Covers initial A stores (h=0) and previous half's W reads (h>0)
        __syncthreads();
        // ---- Load W strip (128 cols x 128 k) hi/lo ----
        {
            int n = tid >> 1;
            int kq = (tid & 1) * 8;  // uint4 index within row
            const uint4* gh = reinterpret_cast<const uint4*>(WHg) +
                              (size_t)(h * 128 + n) * 16 + kq;
            const uint4* gl = reinterpret_cast<const uint4*>(WLg) +
                              (size_t)(h * 128 + n) * 16 + kq;
            uint4* sh = reinterpret_cast<uint4*>(sWH + n * WSTR) + kq;
            uint4* sl = reinterpret_cast<uint4*>(sWL + n * WSTR) + kq;
#pragma unroll
            for (int i = 0; i < 8; i++) {
                sh[i] = gh[i];
                sl[i] = gl[i];
            }
        }
        __syncthreads();

        float acc[64];
#pragma unroll
        for (int i = 0; i < 64; i++) acc[i] = 0.f;

#pragma unroll
        for (int ks = 0; ks < 8; ks++) {
            uint32_t kb = (uint32_t)(ks * 32);
            uint32_t ah0[4], al0[4], ah1[4], al1[4];
            ldsm4(ah0, aA0 + kb);
            ldsm4(al0, aA0 + A_LO + kb);
            ldsm4(ah1, aA0 + A_MB + kb);
            ldsm4(al1, aA0 + A_MB + A_LO + kb);
#pragma unroll
            for (int np = 0; np < 4; np++) {
                uint32_t bh[4], bl[4];
                ldsm4(bh, aB0 + np * B_NP + kb);
                ldsm4(bl, aB0 + B_LO + np * B_NP + kb);
                float* d00 = acc + (0 * 8 + np * 2) * 4;
                float* d01 = acc + (0 * 8 + np * 2 + 1) * 4;
                float* d10 = acc + (1 * 8 + np * 2) * 4;
                float* d11 = acc + (1 * 8 + np * 2 + 1) * 4;
                mma_bf16(d00, ah0, bh[0], bh[1]);
                mma_bf16(d00, ah0, bl[0], bl[1]);
                mma_bf16(d00, al0, bh[0], bh[1]);
                mma_bf16(d01, ah0, bh[2], bh[3]);
                mma_bf16(d01, ah0, bl[2], bl[3]);
                mma_bf16(d01, al0, bh[2], bh[3]);
                mma_bf16(d10, ah1, bh[0], bh[1]);
                mma_bf16(d10, ah1, bl[0], bl[1]);
                mma_bf16(d10, al1, bh[0], bh[1]);
                mma_bf16(d11, ah1, bh[2], bh[3]);
                mma_bf16(d11, ah1, bl[2], bl[3]);
                mma_bf16(d11, al1, bh[2], bh[3]);
            }
        }

        // ---- Flush: rows base + rg*32 + mb*16 + {rq, rq+8}, cols h*128+cg*64+nb*8 ----
        int rq = lane >> 2;
        int cq = 2 * (lane & 3);
#pragma unroll
        for (int mb = 0; mb < 2; mb++) {
#pragma unroll
            for (int nb = 0; nb < 8; nb++) {
                float* d = acc + (mb * 8 + nb) * 4;
                int r0 = base + rg * 32 + mb * 16 + rq;
                int col = h * 128 + cg * 64 + nb * 8 + cq;
                if (r0 < M)
                    *reinterpret_cast<float2*>(&C[(size_t)r0 * NOUT + col]) =
                        make_float2(d[0], d[1]);
                if (r0 + 8 < M)
                    *reinterpret_cast<float2*>(&C[(size_t)(r0 + 8) * NOUT + col]) =
                        make_float2(d[2], d[3]);
            }
        }
    }
}

// ---------------------------------------------------------------------------
// Fused CSR aggregation + epilogue, layer 1.
// ---------------------------------------------------------------------------
__global__ void agg_fin1_kernel(const float* __restrict__ b1) {
    int warp = (blockIdx.x * blockDim.x + threadIdx.x) >> 5;
    int lane = threadIdx.x & 31;
    if (warp >= NNODES) return;
    int node = warp;

    int beg = g_off[node];
    int cnt = g_cnt[node];
    int end = beg + cnt;

    float4 a0 = make_float4(0.f, 0.f, 0.f, 0.f);
    float4 a1 = a0, a2 = a0, a3 = a0;

    int j = beg;
    for (; j + 4 <= end; j += 4) {
        int s0 = g_csr[j];
        int s1 = g_csr[j + 1];
        int s2 = g_csr[j + 2];
        int s3 = g_csr[j + 3];
        a0 = f4add(a0, g_C1[s0 * 64 + 32 + lane]);
        a1 = f4add(a1, g_C1[s1 * 64 + 32 + lane]);
        a2 = f4add(a2, g_C1[s2 * 64 + 32 + lane]);
        a3 = f4add(a3, g_C1[s3 * 64 + 32 + lane]);
    }
    for (; j < end; j++) {
        int s = g_csr[j];
        a0 = f4add(a0, g_C1[s * 64 + 32 + lane]);
    }
    float4 sum = f4add(f4add(a0, a1), f4add(a2, a3));

    float rdeg = 1.0f / fmaxf((float)cnt, 1.0f);
    float4 self = g_C1[node * 64 + lane];
    float4 bb = reinterpret_cast<const float4*>(b1)[lane];
    float4 h;
    h.x = fmaxf(fmaf(sum.x, rdeg, self.x) + bb.x, 0.f);
    h.y = fmaxf(fmaf(sum.y, rdeg, self.y) + bb.y, 0.f);
    h.z = fmaxf(fmaf(sum.z, rdeg, self.z) + bb.z, 0.f);
    h.w = fmaxf(fmaf(sum.w, rdeg, self.w) + bb.w, 0.f);
    g_H1[node * 32 + lane] = h;
}

// ---------------------------------------------------------------------------
// Fused CSR aggregation + epilogue, layer 2.
// ---------------------------------------------------------------------------
__global__ void agg_fin2_kernel(const float* __restrict__ b2,
                                float4* __restrict__ out) {
    int grp = (blockIdx.x * blockDim.x + threadIdx.x) >> 4;
    int lane = threadIdx.x & 15;
    if (grp >= NNODES) return;
    int node = grp;

    int beg = g_off[node];
    int cnt = g_cnt[node];
    int end = beg + cnt;

    float4 a0 = make_float4(0.f, 0.f, 0.f, 0.f);
    float4 a1 = a0, a2 = a0, a3 = a0;

    int j = beg;
    for (; j + 4 <= end; j += 4) {
        int s0 = g_csr[j];
        int s1 = g_csr[j + 1];
        int s2 = g_csr[j + 2];
        int s3 = g_csr[j + 3];
        a0 = f4add(a0, g_C2[s0 * 32 + 16 + lane]);
        a1 = f4add(a1, g_C2[s1 * 32 + 16 + lane]);
        a2 = f4add(a2, g_C2[s2 * 32 + 16 + lane]);
        a3 = f4add(a3, g_C2[s3 * 32 + 16 + lane]);
    }
    for (; j < end; j++) {
        int s = g_csr[j];
        a0 = f4add(a0, g_C2[s * 32 + 16 + lane]);
    }
    float4 sum = f4add(f4add(a0, a1), f4add(a2, a3));

    float rdeg = 1.0f / fmaxf((float)cnt, 1.0f);
    float4 self = g_C2[node * 32 + lane];
    float4 bb = reinterpret_cast<const float4*>(b2)[lane];
    float4 o;
    o.x = fmaf(sum.x, rdeg, self.x) + bb.x;
    o.y = fmaf(sum.y, rdeg, self.y) + bb.y;
    o.z = fmaf(sum.z, rdeg, self.z) + bb.z;
    o.w = fmaf(sum.w, rdeg, self.w) + bb.w;
    out[node * 16 + lane] = o;
}

// ---------------------------------------------------------------------------
// Launch. CSR build forked onto a side stream (event fork/join — the
// documented multi-stream capture pattern; produces only edges in the graph),
// overlapped with prep_w + GEMM1 on the main stream.
// ---------------------------------------------------------------------------
extern "C" void kernel_launch(void* const* d_in, const int* in_sizes, int n_in,
                              void* d_out, int out_size) {
    const float* x   = (const float*)d_in[0];
    const float* Ws1 = (const float*)d_in[1];
    const float* Wn1 = (const float*)d_in[2];
    const float* b1  = (const float*)d_in[3];
    const float* Ws2 = (const float*)d_in[4];
    const float* Wn2 = (const float*)d_in[5];
    const float* b2  = (const float*)d_in[6];
    const int*   src = (const int*)d_in[7];
    const int*   dst = (const int*)d_in[8];
    float4* out = (float4*)d_out;

    float* h1 = nullptr; float* c1 = nullptr; float* c2 = nullptr;
    __nv_bfloat16 *w1h = nullptr, *w1l = nullptr, *w2h = nullptr, *w2l = nullptr;
    cudaGetSymbolAddress((void**)&h1,  g_H1);
    cudaGetSymbolAddress((void**)&c1,  g_C1);
    cudaGetSymbolAddress((void**)&c2,  g_C2);
    cudaGetSymbolAddress((void**)&w1h, g_W1H);
    cudaGetSymbolAddress((void**)&w1l, g_W1L);
    cudaGetSymbolAddress((void**)&w2h, g_W2H);
    cudaGetSymbolAddress((void**)&w2l, g_W2L);

    // Lazy one-time stream/event creation (resource init only; the launched
    // work is identical on every call).
    static cudaStream_t s_side = nullptr;
    static cudaEvent_t  s_fork = nullptr, s_join = nullptr;
    if (s_side == nullptr) {
        cudaStreamCreateWithFlags(&s_side, cudaStreamNonBlocking);
        cudaEventCreateWithFlags(&s_fork, cudaEventDisableTiming);
        cudaEventCreateWithFlags(&s_join, cudaEventDisableTiming);
    }

    const int SCAN_BLOCKS = (NNODES + 511) / 512;            // 98
    const int GTILES = (NNODES + 127) / 128;                 // 391
    const int GSMEM = 4 * 128 * 136 * 2;                     // 139264 bytes

    cudaFuncSetAttribute(gemm_mma_kernel<256>,
                         cudaFuncAttributeMaxDynamicSharedMemorySize, GSMEM);
    cudaFuncSetAttribute(gemm_mma_kernel<128>,
                         cudaFuncAttributeMaxDynamicSharedMemorySize, GSMEM);

    // ---- Fork: CSR build on side stream ----
    cudaEventRecord(s_fork, 0);
    cudaStreamWaitEvent(s_side, s_fork, 0);
    zero_cnt_kernel<<<(NNODES + 255) / 256, 256, 0, s_side>>>();
    hist_kernel<<<(NEDGES + 255) / 256, 256, 0, s_side>>>(dst);
    scanA_kernel<<<SCAN_BLOCKS, 512, 0, s_side>>>();
    scanC_kernel<<<(NNODES + 255) / 256, 256, 0, s_side>>>(SCAN_BLOCKS);
    scatter_kernel<<<(NEDGES + 255) / 256, 256, 0, s_side>>>(src, dst);
    cudaEventRecord(s_join, s_side);

    // ---- Main stream: weight prep + GEMM1 (independent of CSR) ----
    prep_w_kernel<<<128, 256>>>(Ws1, Wn1, Ws2, Wn2);
    gemm_mma_kernel<256><<<GTILES, 256, GSMEM>>>(x, w1h, w1l, c1, NNODES);

    // ---- Join: aggregation needs CSR ----
    cudaStreamWaitEvent(0, s_join, 0);
    agg_fin1_kernel<<<(NNODES * 32 + 255) / 256, 256>>>(b1);

    gemm_mma_kernel<128><<<GTILES, 256, GSMEM>>>(h1, w2h, w2l, c2, NNODES);
    agg_fin2_kernel<<<(NNODES * 16 + 255) / 256, 256>>>(b2, out);
}

// round 6
// speedup vs baseline: 2.1924x; 1.0689x over previous
#include <cuda_runtime.h>
#include <cuda_bf16.h>
#include <cuda_fp16.h>
#include <cstdint>

// Problem constants (match reference setup_inputs)
#define NNODES 50000
#define NEDGES 640000
// IN_DIM = 128, HID = 128, OUT = 64

// ---------------------------------------------------------------------------
// Device scratch (allocation-free rule: __device__ globals)
// ---------------------------------------------------------------------------
__device__ float  g_C1s[NNODES * 128];    // layer1 self projection (fp32)
__device__ __half g_P1[NNODES * 128];     // layer1 neighbor projection (fp16)
__device__ float4 g_H1[NNODES * 32];      // hidden activations [N,128]
__device__ float  g_C2s[NNODES * 64];     // layer2 self projection (fp32)
__device__ __half g_P2[NNODES * 64];      // layer2 neighbor projection (fp16)
// bf16 hi/lo split weights, plain [n][k] row-major (k contiguous)
__device__ __align__(16) __nv_bfloat16 g_W1H[256 * 128];
__device__ __align__(16) __nv_bfloat16 g_W1L[256 * 128];
__device__ __align__(16) __nv_bfloat16 g_W2H[128 * 128];
__device__ __align__(16) __nv_bfloat16 g_W2L[128 * 128];
// CSR build scratch
__device__ int    g_cnt[NNODES];
__device__ int    g_off[NNODES];
__device__ int    g_cur[NNODES];
__device__ int    g_csr[NEDGES];
__device__ int    g_blkSums[128];

// ---------------------------------------------------------------------------
// Helpers
// ---------------------------------------------------------------------------
__device__ __forceinline__ uint32_t smem_u32(const void* p) {
    uint32_t a;
    asm("{ .reg .u64 t; cvta.to.shared.u64 t, %1; cvt.u32.u64 %0, t; }"
        : "=r"(a) : "l"(p));
    return a;
}
__device__ __forceinline__ void ldsm4(uint32_t* r, uint32_t addr) {
    asm volatile("ldmatrix.sync.aligned.m8n8.x4.shared.b16 {%0,%1,%2,%3}, [%4];"
                 : "=r"(r[0]), "=r"(r[1]), "=r"(r[2]), "=r"(r[3]) : "r"(addr));
}
__device__ __forceinline__ void mma_bf16(float* d, const uint32_t* a,
                                         uint32_t b0, uint32_t b1) {
    asm volatile(
        "mma.sync.aligned.m16n8k16.row.col.f32.bf16.bf16.f32 "
        "{%0,%1,%2,%3}, {%4,%5,%6,%7}, {%8,%9}, {%0,%1,%2,%3};"
        : "+f"(d[0]), "+f"(d[1]), "+f"(d[2]), "+f"(d[3])
        : "r"(a[0]), "r"(a[1]), "r"(a[2]), "r"(a[3]), "r"(b0), "r"(b1));
}
__device__ __forceinline__ float4 f4add(float4 a, float4 b) {
    return make_float4(a.x + b.x, a.y + b.y, a.z + b.z, a.w + b.w);
}
// Accumulate 4 fp16 values (as uint2) into a float4
__device__ __forceinline__ float4 f4addh(float4 a, uint2 v) {
    __half2 p0 = *reinterpret_cast<__half2*>(&v.x);
    __half2 p1 = *reinterpret_cast<__half2*>(&v.y);
    float2 f0 = __half22float2(p0);
    float2 f1 = __half22float2(p1);
    return make_float4(a.x + f0.x, a.y + f0.y, a.z + f1.x, a.w + f1.y);
}

// ---------------------------------------------------------------------------
// CSR build: zero counts -> histogram -> scanA -> scanC(+parallel prefix) -> scatter
// ---------------------------------------------------------------------------
__global__ void zero_cnt_kernel() {
    int i = blockIdx.x * blockDim.x + threadIdx.x;
    if (i < NNODES) g_cnt[i] = 0;
}
__global__ void hist_kernel(const int* __restrict__ dst) {
    int e = blockIdx.x * blockDim.x + threadIdx.x;
    if (e < NEDGES) atomicAdd(&g_cnt[dst[e]], 1);
}
__global__ void scanA_kernel() {
    __shared__ int s[512];
    int b = blockIdx.x, t = threadIdx.x;
    int i = b * 512 + t;
    int v = (i < NNODES) ? g_cnt[i] : 0;
    s[t] = v;
    __syncthreads();
#pragma unroll
    for (int d = 1; d < 512; d <<= 1) {
        int x = (t >= d) ? s[t - d] : 0;
        __syncthreads();
        s[t] += x;
        __syncthreads();
    }
    if (i < NNODES) g_off[i] = s[t] - v;
    if (t == 511) g_blkSums[b] = s[t];
}
// scanC: parallel Hillis-Steele inclusive scan of block sums, then add prefix.
__global__ void scanC_kernel(int nblocks) {
    __shared__ int s[128];
    int t = threadIdx.x;
    if (t < 128) s[t] = (t < nblocks) ? g_blkSums[t] : 0;
    __syncthreads();
#pragma unroll
    for (int d = 1; d < 128; d <<= 1) {
        int x = 0;
        if (t < 128 && t >= d) x = s[t - d];
        __syncthreads();
        if (t < 128) s[t] += x;
        __syncthreads();
    }
    int i = blockIdx.x * blockDim.x + t;
    if (i < NNODES) {
        int blk = i >> 9;
        int pre = (blk == 0) ? 0 : s[blk - 1];
        int o = g_off[i] + pre;
        g_off[i] = o;
        g_cur[i] = o;
    }
}
__global__ void scatter_kernel(const int* __restrict__ src,
                               const int* __restrict__ dst) {
    int e = blockIdx.x * blockDim.x + threadIdx.x;
    if (e < NEDGES) {
        int d = dst[e];
        int p = atomicAdd(&g_cur[d], 1);
        g_csr[p] = src[e];
    }
}

// ---------------------------------------------------------------------------
// Weight prep: split fp32 -> bf16 hi/lo, plain [n][k] layout.
// ---------------------------------------------------------------------------
__global__ void prep_w_kernel(const float* __restrict__ Ws1,
                              const float* __restrict__ Wn1,
                              const float* __restrict__ Ws2,
                              const float* __restrict__ Wn2) {
    int i = blockIdx.x * blockDim.x + threadIdx.x;
    if (i < 256 * 128) {
        int n = i >> 7, k = i & 127;
        float w = (n < 128) ? Ws1[n * 128 + k] : Wn1[(n - 128) * 128 + k];
        __nv_bfloat16 h = __float2bfloat16_rn(w);
        g_W1H[i] = h;
        g_W1L[i] = __float2bfloat16_rn(w - __bfloat162float(h));
    }
    if (i < 128 * 128) {
        int n = i >> 7, k = i & 127;
        float w = (n < 64) ? Ws2[n * 128 + k] : Wn2[(n - 64) * 128 + k];
        __nv_bfloat16 h = __float2bfloat16_rn(w);
        g_W2H[i] = h;
        g_W2L[i] = __float2bfloat16_rn(w - __bfloat162float(h));
    }
}

// ---------------------------------------------------------------------------
// Tensor-core GEMM via mma.sync (HMMA), split-bf16 (3 terms, fp32 accum).
// Cols [0, NSELF) -> fp32 Cself (row stride NSELF);
// cols [NSELF, NOUT) -> fp16 Pneigh (row stride NOUT-NSELF).
// CTA = 256 threads (8 warps). Warp tile = 32 rows x 64 cols.
// SMEM: AH[128][136] AL[128][136] WH[128][136] WL[128][136] bf16 (139 KB)
// ---------------------------------------------------------------------------
template <int NOUT, int NSELF>
__global__ void __launch_bounds__(256)
gemm_mma_kernel(const float* __restrict__ A,
                const __nv_bfloat16* __restrict__ WHg,
                const __nv_bfloat16* __restrict__ WLg,
                float* __restrict__ Cself,
                __half* __restrict__ Pneigh, int M) {
    constexpr int ASTR = 136;
    constexpr int WSTR = 136;
    constexpr int NP = NOUT - NSELF;
    extern __shared__ __nv_bfloat16 smem[];
    __nv_bfloat16* sAH = smem;                    // 128*136
    __nv_bfloat16* sAL = sAH + 128 * ASTR;
    __nv_bfloat16* sWH = sAL + 128 * ASTR;        // 128*136
    __nv_bfloat16* sWL = sWH + 128 * WSTR;

    int tid = threadIdx.x;
    int warp = tid >> 5, lane = tid & 31;
    int rg = warp >> 1, cg = warp & 1;
    int base = blockIdx.x * 128;

    // ---- Load A tile (128 rows x 128 fp32), split to bf16 hi/lo in SMEM ----
    {
        int row = tid >> 1;
        int cbase = (tid & 1) * 64;
        int grow = base + row;
        const float4* A4 = reinterpret_cast<const float4*>(A);
#pragma unroll
        for (int i = 0; i < 8; i++) {
            float4 u, v;
            if (grow < M) {
                u = A4[(size_t)grow * 32 + (cbase >> 2) + 2 * i];
                v = A4[(size_t)grow * 32 + (cbase >> 2) + 2 * i + 1];
            } else {
                u = v = make_float4(0.f, 0.f, 0.f, 0.f);
            }
            float f[8] = {u.x, u.y, u.z, u.w, v.x, v.y, v.z, v.w};
            alignas(16) __nv_bfloat16 hb[8], lb[8];
#pragma unroll
            for (int q = 0; q < 8; q++) {
                __nv_bfloat16 h = __float2bfloat16_rn(f[q]);
                hb[q] = h;
                lb[q] = __float2bfloat16_rn(f[q] - __bfloat162float(h));
            }
            int off = row * ASTR + cbase + 8 * i;
            *reinterpret_cast<uint4*>(sAH + off) = *reinterpret_cast<uint4*>(hb);
            *reinterpret_cast<uint4*>(sAL + off) = *reinterpret_cast<uint4*>(lb);
        }
    }

    // Per-thread ldmatrix base offsets
    int g8 = lane >> 3, j8 = lane & 7;
    uint32_t aA0 = smem_u32(sAH) +
                   (uint32_t)(((rg * 32 + (g8 & 1) * 8 + j8) * ASTR + (g8 >> 1) * 8) * 2);
    constexpr uint32_t A_MB = 16u * ASTR * 2u;        // m-block stride
    constexpr uint32_t A_LO = 128u * ASTR * 2u;       // hi->lo plane
    uint32_t aB0 = smem_u32(sWH) +
                   (uint32_t)(((cg * 64 + (g8 >> 1) * 8 + j8) * WSTR + (g8 & 1) * 8) * 2);
    constexpr uint32_t B_NP = 16u * WSTR * 2u;        // nblk-pair stride
    constexpr uint32_t B_LO = 128u * WSTR * 2u;       // hi->lo plane

#pragma unroll
    for (int h = 0; h < NOUT / 128; h++) {
        __syncthreads();
        // ---- Load W strip (128 cols x 128 k) hi/lo ----
        {
            int n = tid >> 1;
            int kq = (tid & 1) * 8;
            const uint4* gh = reinterpret_cast<const uint4*>(WHg) +
                              (size_t)(h * 128 + n) * 16 + kq;
            const uint4* gl = reinterpret_cast<const uint4*>(WLg) +
                              (size_t)(h * 128 + n) * 16 + kq;
            uint4* sh = reinterpret_cast<uint4*>(sWH + n * WSTR) + kq;
            uint4* sl = reinterpret_cast<uint4*>(sWL + n * WSTR) + kq;
#pragma unroll
            for (int i = 0; i < 8; i++) {
                sh[i] = gh[i];
                sl[i] = gl[i];
            }
        }
        __syncthreads();

        float acc[64];
#pragma unroll
        for (int i = 0; i < 64; i++) acc[i] = 0.f;

#pragma unroll
        for (int ks = 0; ks < 8; ks++) {
            uint32_t kb = (uint32_t)(ks * 32);
            uint32_t ah0[4], al0[4], ah1[4], al1[4];
            ldsm4(ah0, aA0 + kb);
            ldsm4(al0, aA0 + A_LO + kb);
            ldsm4(ah1, aA0 + A_MB + kb);
            ldsm4(al1, aA0 + A_MB + A_LO + kb);
#pragma unroll
            for (int np = 0; np < 4; np++) {
                uint32_t bh[4], bl[4];
                ldsm4(bh, aB0 + np * B_NP + kb);
                ldsm4(bl, aB0 + B_LO + np * B_NP + kb);
                float* d00 = acc + (0 * 8 + np * 2) * 4;
                float* d01 = acc + (0 * 8 + np * 2 + 1) * 4;
                float* d10 = acc + (1 * 8 + np * 2) * 4;
                float* d11 = acc + (1 * 8 + np * 2 + 1) * 4;
                mma_bf16(d00, ah0, bh[0], bh[1]);
                mma_bf16(d00, ah0, bl[0], bl[1]);
                mma_bf16(d00, al0, bh[0], bh[1]);
                mma_bf16(d01, ah0, bh[2], bh[3]);
                mma_bf16(d01, ah0, bl[2], bl[3]);
                mma_bf16(d01, al0, bh[2], bh[3]);
                mma_bf16(d10, ah1, bh[0], bh[1]);
                mma_bf16(d10, ah1, bl[0], bl[1]);
                mma_bf16(d10, al1, bh[0], bh[1]);
                mma_bf16(d11, ah1, bh[2], bh[3]);
                mma_bf16(d11, ah1, bl[2], bl[3]);
                mma_bf16(d11, al1, bh[2], bh[3]);
            }
        }

        // ---- Flush ----
        int rq = lane >> 2;
        int cq = 2 * (lane & 3);
#pragma unroll
        for (int mb = 0; mb < 2; mb++) {
#pragma unroll
            for (int nb = 0; nb < 8; nb++) {
                float* d = acc + (mb * 8 + nb) * 4;
                int r0 = base + rg * 32 + mb * 16 + rq;
                int col = h * 128 + cg * 64 + nb * 8 + cq;
                if (col < NSELF) {
                    if (r0 < M)
                        *reinterpret_cast<float2*>(&Cself[(size_t)r0 * NSELF + col]) =
                            make_float2(d[0], d[1]);
                    if (r0 + 8 < M)
                        *reinterpret_cast<float2*>(&Cself[(size_t)(r0 + 8) * NSELF + col]) =
                            make_float2(d[2], d[3]);
                } else {
                    int pc = col - NSELF;
                    if (r0 < M)
                        *reinterpret_cast<__half2*>(&Pneigh[(size_t)r0 * NP + pc]) =
                            __floats2half2_rn(d[0], d[1]);
                    if (r0 + 8 < M)
                        *reinterpret_cast<__half2*>(&Pneigh[(size_t)(r0 + 8) * NP + pc]) =
                            __floats2half2_rn(d[2], d[3]);
                }
            }
        }
    }
}

// ---------------------------------------------------------------------------
// Fused CSR aggregation + epilogue, layer 1 (fp16 gathers).
// Warp per node: 32 lanes x 4 halves (uint2) = 128-value row.
// ---------------------------------------------------------------------------
__global__ void agg_fin1_kernel(const float* __restrict__ b1) {
    int warp = (blockIdx.x * blockDim.x + threadIdx.x) >> 5;
    int lane = threadIdx.x & 31;
    if (warp >= NNODES) return;
    int node = warp;

    int beg = g_off[node];
    int cnt = g_cnt[node];
    int end = beg + cnt;

    const uint2* P = reinterpret_cast<const uint2*>(g_P1);
    float4 a0 = make_float4(0.f, 0.f, 0.f, 0.f);
    float4 a1 = a0, a2 = a0, a3 = a0;

    int j = beg;
    for (; j + 4 <= end; j += 4) {
        int s0 = g_csr[j];
        int s1 = g_csr[j + 1];
        int s2 = g_csr[j + 2];
        int s3 = g_csr[j + 3];
        a0 = f4addh(a0, P[s0 * 32 + lane]);
        a1 = f4addh(a1, P[s1 * 32 + lane]);
        a2 = f4addh(a2, P[s2 * 32 + lane]);
        a3 = f4addh(a3, P[s3 * 32 + lane]);
    }
    for (; j < end; j++) {
        int s = g_csr[j];
        a0 = f4addh(a0, P[s * 32 + lane]);
    }
    float4 sum = f4add(f4add(a0, a1), f4add(a2, a3));

    float rdeg = 1.0f / fmaxf((float)cnt, 1.0f);
    float4 self = reinterpret_cast<const float4*>(g_C1s)[node * 32 + lane];
    float4 bb = reinterpret_cast<const float4*>(b1)[lane];
    float4 h;
    h.x = fmaxf(fmaf(sum.x, rdeg, self.x) + bb.x, 0.f);
    h.y = fmaxf(fmaf(sum.y, rdeg, self.y) + bb.y, 0.f);
    h.z = fmaxf(fmaf(sum.z, rdeg, self.z) + bb.z, 0.f);
    h.w = fmaxf(fmaf(sum.w, rdeg, self.w) + bb.w, 0.f);
    g_H1[node * 32 + lane] = h;
}

// ---------------------------------------------------------------------------
// Fused CSR aggregation + epilogue, layer 2 (fp16 gathers).
// 16-lane group per node: 16 x 4 halves = 64-value row.
// ---------------------------------------------------------------------------
__global__ void agg_fin2_kernel(const float* __restrict__ b2,
                                float4* __restrict__ out) {
    int grp = (blockIdx.x * blockDim.x + threadIdx.x) >> 4;
    int lane = threadIdx.x & 15;
    if (grp >= NNODES) return;
    int node = grp;

    int beg = g_off[node];
    int cnt = g_cnt[node];
    int end = beg + cnt;

    const uint2* P = reinterpret_cast<const uint2*>(g_P2);
    float4 a0 = make_float4(0.f, 0.f, 0.f, 0.f);
    float4 a1 = a0, a2 = a0, a3 = a0;

    int j = beg;
    for (; j + 4 <= end; j += 4) {
        int s0 = g_csr[j];
        int s1 = g_csr[j + 1];
        int s2 = g_csr[j + 2];
        int s3 = g_csr[j + 3];
        a0 = f4addh(a0, P[s0 * 16 + lane]);
        a1 = f4addh(a1, P[s1 * 16 + lane]);
        a2 = f4addh(a2, P[s2 * 16 + lane]);
        a3 = f4addh(a3, P[s3 * 16 + lane]);
    }
    for (; j < end; j++) {
        int s = g_csr[j];
        a0 = f4addh(a0, P[s * 16 + lane]);
    }
    float4 sum = f4add(f4add(a0, a1), f4add(a2, a3));

    float rdeg = 1.0f / fmaxf((float)cnt, 1.0f);
    float4 self = reinterpret_cast<const float4*>(g_C2s)[node * 16 + lane];
    float4 bb = reinterpret_cast<const float4*>(b2)[lane];
    float4 o;
    o.x = fmaf(sum.x, rdeg, self.x) + bb.x;
    o.y = fmaf(sum.y, rdeg, self.y) + bb.y;
    o.z = fmaf(sum.z, rdeg, self.z) + bb.z;
    o.w = fmaf(sum.w, rdeg, self.w) + bb.w;
    out[node * 16 + lane] = o;
}

// ---------------------------------------------------------------------------
// Launch. CSR build forked onto a side stream, overlapped with prep_w + GEMM1.
// ---------------------------------------------------------------------------
extern "C" void kernel_launch(void* const* d_in, const int* in_sizes, int n_in,
                              void* d_out, int out_size) {
    const float* x   = (const float*)d_in[0];
    const float* Ws1 = (const float*)d_in[1];
    const float* Wn1 = (const float*)d_in[2];
    const float* b1  = (const float*)d_in[3];
    const float* Ws2 = (const float*)d_in[4];
    const float* Wn2 = (const float*)d_in[5];
    const float* b2  = (const float*)d_in[6];
    const int*   src = (const int*)d_in[7];
    const int*   dst = (const int*)d_in[8];
    float4* out = (float4*)d_out;

    float *c1s = nullptr, *c2s = nullptr, *h1 = nullptr;
    __half *p1 = nullptr, *p2 = nullptr;
    __nv_bfloat16 *w1h = nullptr, *w1l = nullptr, *w2h = nullptr, *w2l = nullptr;
    cudaGetSymbolAddress((void**)&c1s, g_C1s);
    cudaGetSymbolAddress((void**)&p1,  g_P1);
    cudaGetSymbolAddress((void**)&h1,  g_H1);
    cudaGetSymbolAddress((void**)&c2s, g_C2s);
    cudaGetSymbolAddress((void**)&p2,  g_P2);
    cudaGetSymbolAddress((void**)&w1h, g_W1H);
    cudaGetSymbolAddress((void**)&w1l, g_W1L);
    cudaGetSymbolAddress((void**)&w2h, g_W2H);
    cudaGetSymbolAddress((void**)&w2l, g_W2L);

    static cudaStream_t s_side = nullptr;
    static cudaEvent_t  s_fork = nullptr, s_join = nullptr;
    if (s_side == nullptr) {
        cudaStreamCreateWithFlags(&s_side, cudaStreamNonBlocking);
        cudaEventCreateWithFlags(&s_fork, cudaEventDisableTiming);
        cudaEventCreateWithFlags(&s_join, cudaEventDisableTiming);
    }

    const int SCAN_BLOCKS = (NNODES + 511) / 512;            // 98
    const int GTILES = (NNODES + 127) / 128;                 // 391
    const int GSMEM = 4 * 128 * 136 * 2;                     // 139264 bytes

    cudaFuncSetAttribute((const void*)gemm_mma_kernel<256, 128>,
                         cudaFuncAttributeMaxDynamicSharedMemorySize, GSMEM);
    cudaFuncSetAttribute((const void*)gemm_mma_kernel<128, 64>,
                         cudaFuncAttributeMaxDynamicSharedMemorySize, GSMEM);

    // ---- Fork: CSR build on side stream ----
    cudaEventRecord(s_fork, 0);
    cudaStreamWaitEvent(s_side, s_fork, 0);
    zero_cnt_kernel<<<(NNODES + 255) / 256, 256, 0, s_side>>>();
    hist_kernel<<<(NEDGES + 255) / 256, 256, 0, s_side>>>(dst);
    scanA_kernel<<<SCAN_BLOCKS, 512, 0, s_side>>>();
    scanC_kernel<<<(NNODES + 255) / 256, 256, 0, s_side>>>(SCAN_BLOCKS);
    scatter_kernel<<<(NEDGES + 255) / 256, 256, 0, s_side>>>(src, dst);
    cudaEventRecord(s_join, s_side);

    // ---- Main stream: weight prep + GEMM1 (independent of CSR) ----
    prep_w_kernel<<<128, 256>>>(Ws1, Wn1, Ws2, Wn2);
    gemm_mma_kernel<256, 128><<<GTILES, 256, GSMEM>>>(x, w1h, w1l, c1s, p1, NNODES);

    // ---- Join: aggregation needs CSR ----
    cudaStreamWaitEvent(0, s_join, 0);
    agg_fin1_kernel<<<(NNODES * 32 + 255) / 256, 256>>>(b1);

    gemm_mma_kernel<128, 64><<<GTILES, 256, GSMEM>>>(h1, w2h, w2l, c2s, p2, NNODES);
    agg_fin2_kernel<<<(NNODES * 16 + 255) / 256, 256>>>(b2, out);
}